// round 1
// baseline (speedup 1.0000x reference)
#include <cuda_runtime.h>

// Problem constants
#define Cc 3
#define Hh 512
#define Ww 512
#define NPIX (Hh*Ww)          // 262144 = 2^18
#define MAXB 64

// Tile config
#define TW 64
#define TH 16
#define SW (TW+2)             // 66
#define SH (TH+2)             // 18
#define NB_X (Ww/TW)          // 8
#define NB_Y (Hh/TH)          // 32
#define NBLK_MAX (NB_X*NB_Y*MAXB)  // 16384

// Scratch (static device globals; no allocation in kernel_launch)
__device__ float g_y1[(size_t)MAXB*Cc*NPIX];
__device__ float g_y2[(size_t)MAXB*Cc*NPIX];
__device__ float g_part1[NBLK_MAX*6];
__device__ float g_part2[NBLK_MAX*6];
__device__ float g_bn1[6];   // [0..2] = A (scale), [3..5] = B (bias) per channel
__device__ float g_bn2[6];

__device__ __forceinline__ float ratf(float x,
    float a0, float a1, float a2, float a3, float a4, float a5,
    float b0, float b1, float b2, float b3)
{
    float P = fmaf(x, fmaf(x, fmaf(x, fmaf(x, fmaf(x, a5, a4), a3), a2), a1), a0);
    float q = fmaf(x, fmaf(x, fmaf(x, b3, b2), b1), b0);
    float Q = 1.0f + fabsf(x * q);
    return P / Q;
}

// Fused conv3x3 (+ optional BN1-affine + rational pre-activation on input) + stats.
// PRE=false: in = x (param), out = g_y1, partials = g_part1
// PRE=true : in = g_y1,      out = g_y2, partials = g_part2
template<bool PRE>
__global__ __launch_bounds__(256)
void conv_kernel(const float* __restrict__ xin, const float* __restrict__ w,
                 const float* __restrict__ ar, const float* __restrict__ br,
                 const float* __restrict__ ag, const float* __restrict__ bg,
                 const float* __restrict__ ab, const float* __restrict__ bb)
{
    __shared__ float s[Cc][SH][SW];
    __shared__ float sred[8][6];

    const int b  = blockIdx.z;
    const int h0 = blockIdx.y * TH;
    const int w0 = blockIdx.x * TW;
    const int tid = threadIdx.x;

    const float* in = PRE ? (const float*)g_y1 : xin;
    float* outbuf   = PRE ? g_y2 : g_y1;
    float* part     = PRE ? g_part2 : g_part1;

    // ---- fill shared tile (with SAME zero padding), optional BN1+rational ----
    #pragma unroll
    for (int c = 0; c < Cc; c++) {
        float A = 0.f, Bv = 0.f;
        float a0=0,a1=0,a2=0,a3=0,a4=0,a5=0,q0=0,q1=0,q2=0,q3=0;
        if (PRE) {
            A  = g_bn1[c];
            Bv = g_bn1[3 + c];
            const float* A6 = (c == 0) ? ar : ((c == 1) ? ag : ab);
            const float* B4 = (c == 0) ? br : ((c == 1) ? bg : bb);
            a0 = __ldg(&A6[0]); a1 = __ldg(&A6[1]); a2 = __ldg(&A6[2]);
            a3 = __ldg(&A6[3]); a4 = __ldg(&A6[4]); a5 = __ldg(&A6[5]);
            q0 = __ldg(&B4[0]); q1 = __ldg(&B4[1]); q2 = __ldg(&B4[2]); q3 = __ldg(&B4[3]);
        }
        const float* base = in + ((size_t)b * Cc + c) * NPIX;
        for (int i = tid; i < SH * SW; i += 256) {
            int r   = i / SW;
            int col = i - r * SW;
            int gh = h0 - 1 + r;
            int gw = w0 - 1 + col;
            float v = 0.0f;
            if (gh >= 0 && gh < Hh && gw >= 0 && gw < Ww)
                v = base[gh * Ww + gw];
            if (PRE) {
                float t = fmaf(v, A, Bv);
                v = ratf(t, a0, a1, a2, a3, a4, a5, q0, q1, q2, q3);
            }
            s[c][r][col] = v;
        }
    }
    __syncthreads();

    // ---- weights into registers (OIHW) ----
    float wl[3][3][3][3];
    #pragma unroll
    for (int co = 0; co < 3; co++)
        #pragma unroll
        for (int ci = 0; ci < 3; ci++)
            #pragma unroll
            for (int ky = 0; ky < 3; ky++)
                #pragma unroll
                for (int kx = 0; kx < 3; kx++)
                    wl[co][ci][ky][kx] = __ldg(&w[((co * 3 + ci) * 3 + ky) * 3 + kx]);

    // ---- compute: each thread does 4 horizontally adjacent pixels x 3 out channels ----
    const int tx = tid & 15;        // 16 col-groups of 4
    const int ty = tid >> 4;        // 16 rows
    const int col0 = tx * 4;

    float acc[3][4];
    #pragma unroll
    for (int co = 0; co < 3; co++)
        #pragma unroll
        for (int px = 0; px < 4; px++)
            acc[co][px] = 0.0f;

    #pragma unroll
    for (int ci = 0; ci < 3; ci++) {
        #pragma unroll
        for (int ky = 0; ky < 3; ky++) {
            float v[6];
            #pragma unroll
            for (int j = 0; j < 6; j++)
                v[j] = s[ci][ty + ky][col0 + j];
            #pragma unroll
            for (int kx = 0; kx < 3; kx++)
                #pragma unroll
                for (int co = 0; co < 3; co++)
                    #pragma unroll
                    for (int px = 0; px < 4; px++)
                        acc[co][px] = fmaf(wl[co][ci][ky][kx], v[px + kx], acc[co][px]);
        }
    }

    // ---- store results (float4) + accumulate per-thread stats ----
    float st[6];
    #pragma unroll
    for (int k = 0; k < 6; k++) st[k] = 0.0f;

    #pragma unroll
    for (int co = 0; co < 3; co++) {
        float4 o;
        o.x = acc[co][0]; o.y = acc[co][1]; o.z = acc[co][2]; o.w = acc[co][3];
        st[co]     += o.x + o.y + o.z + o.w;
        st[co + 3] += o.x*o.x + o.y*o.y + o.z*o.z + o.w*o.w;
        size_t off = ((size_t)b * Cc + co) * NPIX + (size_t)(h0 + ty) * Ww + (w0 + col0);
        *reinterpret_cast<float4*>(outbuf + off) = o;
    }

    // ---- block reduction (deterministic per-block partials) ----
    #pragma unroll
    for (int off = 16; off > 0; off >>= 1)
        #pragma unroll
        for (int k = 0; k < 6; k++)
            st[k] += __shfl_down_sync(0xffffffffu, st[k], off);

    const int warp = tid >> 5, lane = tid & 31;
    if (lane == 0)
        #pragma unroll
        for (int k = 0; k < 6; k++) sred[warp][k] = st[k];
    __syncthreads();

    if (tid < 6) {
        float t = 0.0f;
        #pragma unroll
        for (int wp = 0; wp < 8; wp++) t += sred[wp][tid];
        int bid = (blockIdx.z * NB_Y + blockIdx.y) * NB_X + blockIdx.x;
        part[bid * 6 + tid] = t;
    }
}

// Reduce partials -> fold BN into per-channel (A, B). which: 0 -> bn1, 1 -> bn2.
__global__ __launch_bounds__(256)
void finalize_kernel(const float* __restrict__ gamma, const float* __restrict__ beta,
                     int nblk, double invN, int which)
{
    __shared__ double sd[256][6];
    const float* part = which ? g_part2 : g_part1;
    float* bn = which ? g_bn2 : g_bn1;
    const int tid = threadIdx.x;

    double acc[6] = {0, 0, 0, 0, 0, 0};
    for (int i = tid; i < nblk; i += 256)
        #pragma unroll
        for (int k = 0; k < 6; k++)
            acc[k] += (double)part[i * 6 + k];
    #pragma unroll
    for (int k = 0; k < 6; k++) sd[tid][k] = acc[k];
    __syncthreads();

    for (int off = 128; off > 0; off >>= 1) {
        if (tid < off)
            #pragma unroll
            for (int k = 0; k < 6; k++)
                sd[tid][k] += sd[tid + off][k];
        __syncthreads();
    }

    if (tid < 3) {
        int c = tid;
        double mean = sd[0][c] * invN;
        double var  = sd[0][c + 3] * invN - mean * mean;
        float A = gamma[c] / sqrtf((float)var + 1e-5f);
        bn[c]     = A;
        bn[3 + c] = beta[c] - (float)mean * A;
    }
}

// Epilogue: out = rational_c(A2*y2 + B2 + x), fully vectorized float4 stream.
__global__ __launch_bounds__(256)
void epilogue_kernel(const float* __restrict__ x, float* __restrict__ out,
                     const float* __restrict__ ar, const float* __restrict__ br,
                     const float* __restrict__ ag, const float* __restrict__ bg,
                     const float* __restrict__ ab, const float* __restrict__ bb,
                     int total4)
{
    int i = blockIdx.x * blockDim.x + threadIdx.x;
    if (i >= total4) return;

    int c = (i >> 16) % 3;    // NPIX/4 = 65536 float4 per channel
    float A  = g_bn2[c];
    float Bv = g_bn2[3 + c];
    const float* A6 = (c == 0) ? ar : ((c == 1) ? ag : ab);
    const float* B4 = (c == 0) ? br : ((c == 1) ? bg : bb);
    float a0 = __ldg(&A6[0]), a1 = __ldg(&A6[1]), a2 = __ldg(&A6[2]);
    float a3 = __ldg(&A6[3]), a4 = __ldg(&A6[4]), a5 = __ldg(&A6[5]);
    float q0 = __ldg(&B4[0]), q1 = __ldg(&B4[1]), q2 = __ldg(&B4[2]), q3 = __ldg(&B4[3]);

    float4 y  = reinterpret_cast<const float4*>(g_y2)[i];
    float4 xv = reinterpret_cast<const float4*>(x)[i];

    float4 o;
    {
        float t = fmaf(y.x, A, Bv) + xv.x;
        o.x = ratf(t, a0, a1, a2, a3, a4, a5, q0, q1, q2, q3);
    }
    {
        float t = fmaf(y.y, A, Bv) + xv.y;
        o.y = ratf(t, a0, a1, a2, a3, a4, a5, q0, q1, q2, q3);
    }
    {
        float t = fmaf(y.z, A, Bv) + xv.z;
        o.z = ratf(t, a0, a1, a2, a3, a4, a5, q0, q1, q2, q3);
    }
    {
        float t = fmaf(y.w, A, Bv) + xv.w;
        o.w = ratf(t, a0, a1, a2, a3, a4, a5, q0, q1, q2, q3);
    }
    reinterpret_cast<float4*>(out)[i] = o;
}

extern "C" void kernel_launch(void* const* d_in, const int* in_sizes, int n_in,
                              void* d_out, int out_size)
{
    const float* x  = (const float*)d_in[0];
    const float* w1 = (const float*)d_in[1];
    const float* g1 = (const float*)d_in[2];
    const float* b1 = (const float*)d_in[3];
    const float* ar = (const float*)d_in[4];
    const float* br = (const float*)d_in[5];
    const float* ag = (const float*)d_in[6];
    const float* bg = (const float*)d_in[7];
    const float* ab = (const float*)d_in[8];
    const float* bb = (const float*)d_in[9];
    const float* w2 = (const float*)d_in[10];
    const float* g2 = (const float*)d_in[11];
    const float* b2 = (const float*)d_in[12];
    float* out = (float*)d_out;

    const int B = in_sizes[0] / (Cc * NPIX);   // 64
    const int nblk = NB_X * NB_Y * B;
    const double invN = 1.0 / ((double)B * (double)NPIX);

    dim3 grid(NB_X, NB_Y, B), block(256);

    // K1: conv1 + stats1
    conv_kernel<false><<<grid, block>>>(x, w1, ar, br, ag, bg, ab, bb);
    // F1: BN1 fold
    finalize_kernel<<<1, 256>>>(g1, b1, nblk, invN, 0);
    // K2: BN1+rational (in-tile) + conv2 + stats2
    conv_kernel<true><<<grid, block>>>(x, w2, ar, br, ag, bg, ab, bb);
    // F2: BN2 fold
    finalize_kernel<<<1, 256>>>(g2, b2, nblk, invN, 1);
    // K3: BN2 + residual + rational -> out
    int total4 = (B * Cc * NPIX) / 4;
    int nb3 = (total4 + 255) / 256;
    epilogue_kernel<<<nb3, 256>>>(x, out, ar, br, ag, bg, ab, bb, total4);
}

// round 3
// speedup vs baseline: 1.1961x; 1.1961x over previous
#include <cuda_runtime.h>

// Problem constants
#define Cc 3
#define Hh 512
#define Ww 512
#define NPIX (Hh*Ww)          // 262144 = 2^18
#define MAXB 64

// Tile config
#define TW 64
#define TH 16
#define SW (TW+2)             // 66
#define SH (TH+2)             // 18
#define NB_X (Ww/TW)          // 8
#define NB_Y (Hh/TH)          // 32
#define NBLK_MAX (NB_X*NB_Y*MAXB)  // 16384

// Scratch (static device globals; no allocation in kernel_launch)
__device__ float g_y1[(size_t)MAXB*Cc*NPIX];
__device__ float g_y2[(size_t)MAXB*Cc*NPIX];
__device__ float g_part1[NBLK_MAX*6];
__device__ float g_part2[NBLK_MAX*6];
__device__ double g_mid[MAXB*6];
__device__ float g_bn1[6];   // [0..2] = A (scale), [3..5] = B (bias) per channel
__device__ float g_bn2[6];

__device__ __forceinline__ float ratf(float x,
    float a0, float a1, float a2, float a3, float a4, float a5,
    float b0, float b1, float b2, float b3)
{
    float P = fmaf(x, fmaf(x, fmaf(x, fmaf(x, fmaf(x, a5, a4), a3), a2), a1), a0);
    float q = fmaf(x, fmaf(x, fmaf(x, b3, b2), b1), b0);
    float Q = 1.0f + fabsf(x * q);
    return P / Q;
}

// Fused conv3x3 (+ optional BN1-affine + rational pre-activation on input) + stats.
// PRE=false: in = x (param), out = g_y1, partials = g_part1
// PRE=true : in = g_y1,      out = g_y2, partials = g_part2
// NOTE: for PRE=true the activation is applied ONLY to in-bounds pixels; the
// SAME zero padding of conv2's input must remain exactly 0 (activated-tensor
// padding), matching the reference.
template<bool PRE>
__global__ __launch_bounds__(256)
void conv_kernel(const float* __restrict__ xin, const float* __restrict__ w,
                 const float* __restrict__ ar, const float* __restrict__ br,
                 const float* __restrict__ ag, const float* __restrict__ bg,
                 const float* __restrict__ ab, const float* __restrict__ bb)
{
    __shared__ float s[Cc][SH][SW];
    __shared__ float sred[8][6];

    const int b  = blockIdx.z;
    const int h0 = blockIdx.y * TH;
    const int w0 = blockIdx.x * TW;
    const int tid = threadIdx.x;

    const float* in = PRE ? (const float*)g_y1 : xin;
    float* outbuf   = PRE ? g_y2 : g_y1;
    float* part     = PRE ? g_part2 : g_part1;

    // ---- fill shared tile (with SAME zero padding), optional BN1+rational ----
    #pragma unroll
    for (int c = 0; c < Cc; c++) {
        float A = 0.f, Bv = 0.f;
        float a0=0,a1=0,a2=0,a3=0,a4=0,a5=0,q0=0,q1=0,q2=0,q3=0;
        if (PRE) {
            A  = g_bn1[c];
            Bv = g_bn1[3 + c];
            const float* A6 = (c == 0) ? ar : ((c == 1) ? ag : ab);
            const float* B4 = (c == 0) ? br : ((c == 1) ? bg : bb);
            a0 = __ldg(&A6[0]); a1 = __ldg(&A6[1]); a2 = __ldg(&A6[2]);
            a3 = __ldg(&A6[3]); a4 = __ldg(&A6[4]); a5 = __ldg(&A6[5]);
            q0 = __ldg(&B4[0]); q1 = __ldg(&B4[1]); q2 = __ldg(&B4[2]); q3 = __ldg(&B4[3]);
        }
        const float* base = in + ((size_t)b * Cc + c) * NPIX;
        for (int i = tid; i < SH * SW; i += 256) {
            int r   = i / SW;
            int col = i - r * SW;
            int gh = h0 - 1 + r;
            int gw = w0 - 1 + col;
            float v = 0.0f;
            if (gh >= 0 && gh < Hh && gw >= 0 && gw < Ww) {
                v = base[gh * Ww + gw];
                if (PRE) {
                    float t = fmaf(v, A, Bv);
                    v = ratf(t, a0, a1, a2, a3, a4, a5, q0, q1, q2, q3);
                }
            }
            s[c][r][col] = v;
        }
    }
    __syncthreads();

    // ---- weights into registers (OIHW) ----
    float wl[3][3][3][3];
    #pragma unroll
    for (int co = 0; co < 3; co++)
        #pragma unroll
        for (int ci = 0; ci < 3; ci++)
            #pragma unroll
            for (int ky = 0; ky < 3; ky++)
                #pragma unroll
                for (int kx = 0; kx < 3; kx++)
                    wl[co][ci][ky][kx] = __ldg(&w[((co * 3 + ci) * 3 + ky) * 3 + kx]);

    // ---- compute: each thread does 4 horizontally adjacent pixels x 3 out channels ----
    const int tx = tid & 15;        // 16 col-groups of 4
    const int ty = tid >> 4;        // 16 rows
    const int col0 = tx * 4;

    float acc[3][4];
    #pragma unroll
    for (int co = 0; co < 3; co++)
        #pragma unroll
        for (int px = 0; px < 4; px++)
            acc[co][px] = 0.0f;

    #pragma unroll
    for (int ci = 0; ci < 3; ci++) {
        #pragma unroll
        for (int ky = 0; ky < 3; ky++) {
            float v[6];
            #pragma unroll
            for (int j = 0; j < 6; j++)
                v[j] = s[ci][ty + ky][col0 + j];
            #pragma unroll
            for (int kx = 0; kx < 3; kx++)
                #pragma unroll
                for (int co = 0; co < 3; co++)
                    #pragma unroll
                    for (int px = 0; px < 4; px++)
                        acc[co][px] = fmaf(wl[co][ci][ky][kx], v[px + kx], acc[co][px]);
        }
    }

    // ---- store results (float4) + accumulate per-thread stats ----
    float st[6];
    #pragma unroll
    for (int k = 0; k < 6; k++) st[k] = 0.0f;

    #pragma unroll
    for (int co = 0; co < 3; co++) {
        float4 o;
        o.x = acc[co][0]; o.y = acc[co][1]; o.z = acc[co][2]; o.w = acc[co][3];
        st[co]     += o.x + o.y + o.z + o.w;
        st[co + 3] += o.x*o.x + o.y*o.y + o.z*o.z + o.w*o.w;
        size_t off = ((size_t)b * Cc + co) * NPIX + (size_t)(h0 + ty) * Ww + (w0 + col0);
        *reinterpret_cast<float4*>(outbuf + off) = o;
    }

    // ---- block reduction (deterministic per-block partials) ----
    #pragma unroll
    for (int off = 16; off > 0; off >>= 1)
        #pragma unroll
        for (int k = 0; k < 6; k++)
            st[k] += __shfl_down_sync(0xffffffffu, st[k], off);

    const int warp = tid >> 5, lane = tid & 31;
    if (lane == 0)
        #pragma unroll
        for (int k = 0; k < 6; k++) sred[warp][k] = st[k];
    __syncthreads();

    if (tid < 6) {
        float t = 0.0f;
        #pragma unroll
        for (int wp = 0; wp < 8; wp++) t += sred[wp][tid];
        int bid = (blockIdx.z * NB_Y + blockIdx.y) * NB_X + blockIdx.x;
        part[bid * 6 + tid] = t;
    }
}

// Stage A: 256 partials per block -> 1 double-precision partial per block.
__global__ __launch_bounds__(256)
void reduceA_kernel(int which)
{
    __shared__ double sd[256][6];
    const float* part = which ? g_part2 : g_part1;
    const int tid = threadIdx.x;
    const int base = (blockIdx.x * 256 + tid) * 6;

    #pragma unroll
    for (int k = 0; k < 6; k++) sd[tid][k] = (double)part[base + k];
    __syncthreads();

    #pragma unroll
    for (int off = 128; off > 0; off >>= 1) {
        if (tid < off)
            #pragma unroll
            for (int k = 0; k < 6; k++)
                sd[tid][k] += sd[tid + off][k];
        __syncthreads();
    }

    if (tid < 6) g_mid[blockIdx.x * 6 + tid] = sd[0][tid];
}

// Stage B: reduce B mid-partials, fold BN into per-channel (A, B).
__global__ __launch_bounds__(256)
void reduceB_kernel(const float* __restrict__ gamma, const float* __restrict__ beta,
                    int nmid, double invN, int which)
{
    __shared__ double sd[256][6];
    float* bn = which ? g_bn2 : g_bn1;
    const int tid = threadIdx.x;

    double acc[6] = {0, 0, 0, 0, 0, 0};
    for (int i = tid; i < nmid; i += 256)
        #pragma unroll
        for (int k = 0; k < 6; k++)
            acc[k] += g_mid[i * 6 + k];
    #pragma unroll
    for (int k = 0; k < 6; k++) sd[tid][k] = acc[k];
    __syncthreads();

    #pragma unroll
    for (int off = 128; off > 0; off >>= 1) {
        if (tid < off)
            #pragma unroll
            for (int k = 0; k < 6; k++)
                sd[tid][k] += sd[tid + off][k];
        __syncthreads();
    }

    if (tid < 3) {
        int c = tid;
        double mean = sd[0][c] * invN;
        double var  = sd[0][c + 3] * invN - mean * mean;
        float A = gamma[c] / sqrtf((float)var + 1e-5f);
        bn[c]     = A;
        bn[3 + c] = beta[c] - (float)mean * A;
    }
}

// Epilogue: out = rational_c(A2*y2 + B2 + x), fully vectorized float4 stream.
__global__ __launch_bounds__(256)
void epilogue_kernel(const float* __restrict__ x, float* __restrict__ out,
                     const float* __restrict__ ar, const float* __restrict__ br,
                     const float* __restrict__ ag, const float* __restrict__ bg,
                     const float* __restrict__ ab, const float* __restrict__ bb,
                     int total4)
{
    int i = blockIdx.x * blockDim.x + threadIdx.x;
    if (i >= total4) return;

    int c = (i >> 16) % 3;    // NPIX/4 = 65536 float4 per channel
    float A  = g_bn2[c];
    float Bv = g_bn2[3 + c];
    const float* A6 = (c == 0) ? ar : ((c == 1) ? ag : ab);
    const float* B4 = (c == 0) ? br : ((c == 1) ? bg : bb);
    float a0 = __ldg(&A6[0]), a1 = __ldg(&A6[1]), a2 = __ldg(&A6[2]);
    float a3 = __ldg(&A6[3]), a4 = __ldg(&A6[4]), a5 = __ldg(&A6[5]);
    float q0 = __ldg(&B4[0]), q1 = __ldg(&B4[1]), q2 = __ldg(&B4[2]), q3 = __ldg(&B4[3]);

    float4 y  = reinterpret_cast<const float4*>(g_y2)[i];
    float4 xv = reinterpret_cast<const float4*>(x)[i];

    float4 o;
    {
        float t = fmaf(y.x, A, Bv) + xv.x;
        o.x = ratf(t, a0, a1, a2, a3, a4, a5, q0, q1, q2, q3);
    }
    {
        float t = fmaf(y.y, A, Bv) + xv.y;
        o.y = ratf(t, a0, a1, a2, a3, a4, a5, q0, q1, q2, q3);
    }
    {
        float t = fmaf(y.z, A, Bv) + xv.z;
        o.z = ratf(t, a0, a1, a2, a3, a4, a5, q0, q1, q2, q3);
    }
    {
        float t = fmaf(y.w, A, Bv) + xv.w;
        o.w = ratf(t, a0, a1, a2, a3, a4, a5, q0, q1, q2, q3);
    }
    reinterpret_cast<float4*>(out)[i] = o;
}

extern "C" void kernel_launch(void* const* d_in, const int* in_sizes, int n_in,
                              void* d_out, int out_size)
{
    const float* x  = (const float*)d_in[0];
    const float* w1 = (const float*)d_in[1];
    const float* g1 = (const float*)d_in[2];
    const float* b1 = (const float*)d_in[3];
    const float* ar = (const float*)d_in[4];
    const float* br = (const float*)d_in[5];
    const float* ag = (const float*)d_in[6];
    const float* bg = (const float*)d_in[7];
    const float* ab = (const float*)d_in[8];
    const float* bb = (const float*)d_in[9];
    const float* w2 = (const float*)d_in[10];
    const float* g2 = (const float*)d_in[11];
    const float* b2 = (const float*)d_in[12];
    float* out = (float*)d_out;

    const int B = in_sizes[0] / (Cc * NPIX);   // 64
    const double invN = 1.0 / ((double)B * (double)NPIX);

    dim3 grid(NB_X, NB_Y, B), block(256);

    // K1: conv1 + stats1
    conv_kernel<false><<<grid, block>>>(x, w1, ar, br, ag, bg, ab, bb);
    // F1: two-stage BN1 fold
    reduceA_kernel<<<B, 256>>>(0);
    reduceB_kernel<<<1, 256>>>(g1, b1, B, invN, 0);
    // K2: BN1+rational (in-tile, in-bounds only) + conv2 + stats2
    conv_kernel<true><<<grid, block>>>(x, w2, ar, br, ag, bg, ab, bb);
    // F2: two-stage BN2 fold
    reduceA_kernel<<<B, 256>>>(1);
    reduceB_kernel<<<1, 256>>>(g2, b2, B, invN, 1);
    // K3: BN2 + residual + rational -> out
    int total4 = (B * Cc * NPIX) / 4;
    int nb3 = (total4 + 255) / 256;
    epilogue_kernel<<<nb3, 256>>>(x, out, ar, br, ag, bg, ab, bb, total4);
}

// round 4
// speedup vs baseline: 1.3429x; 1.1228x over previous
#include <cuda_runtime.h>

// Problem constants
#define Cc 3
#define Hh 512
#define Ww 512
#define NPIX (Hh*Ww)          // 262144
#define MAXB 64

// Tile config: 64 wide x 32 tall, 256 threads, each thread 4w x 2h x 3co
#define TW 64
#define TH 32
#define SW (TW+2)             // 66
#define SH (TH+2)             // 34
#define NB_X (Ww/TW)          // 8
#define NB_Y (Hh/TH)          // 16
#define NPB (NB_X*NB_Y)       // 128 partials per image
#define NBLK_MAX (NPB*MAXB)   // 8192

// Scratch
__device__ float g_y1[(size_t)MAXB*Cc*NPIX];
__device__ float g_y2[(size_t)MAXB*Cc*NPIX];
__device__ float g_part1[NBLK_MAX*6];
__device__ float g_part2[NBLK_MAX*6];
__device__ double g_mid[MAXB*6];
__device__ float g_bn1[6];
__device__ float g_bn2[6];

// ---- packed f32x2 helpers (Blackwell) ----
typedef unsigned long long u64t;
__device__ __forceinline__ u64t pk2(float lo, float hi) {
    u64t r; asm("mov.b64 %0,{%1,%2};" : "=l"(r) : "f"(lo), "f"(hi)); return r;
}
__device__ __forceinline__ void upk2(u64t v, float& lo, float& hi) {
    asm("mov.b64 {%0,%1}, %2;" : "=f"(lo), "=f"(hi) : "l"(v));
}
__device__ __forceinline__ u64t fma2(u64t a, u64t b, u64t c) {
    u64t d; asm("fma.rn.f32x2 %0,%1,%2,%3;" : "=l"(d) : "l"(a), "l"(b), "l"(c)); return d;
}
__device__ __forceinline__ u64t add2(u64t a, u64t b) {
    u64t d; asm("add.rn.f32x2 %0,%1,%2;" : "=l"(d) : "l"(a), "l"(b)); return d;
}

__device__ __forceinline__ float ratf(float x,
    float a0, float a1, float a2, float a3, float a4, float a5,
    float b0, float b1, float b2, float b3)
{
    float P = fmaf(x, fmaf(x, fmaf(x, fmaf(x, fmaf(x, a5, a4), a3), a2), a1), a0);
    float q = fmaf(x, fmaf(x, fmaf(x, b3, b2), b1), b0);
    float Q = 1.0f + fabsf(x * q);
    return __fdividef(P, Q);
}

// Fused conv3x3 (+ optional BN1-affine + rational on input, in-bounds only) + stats.
template<bool PRE>
__global__ __launch_bounds__(256)
void conv_kernel(const float* __restrict__ xin, const float* __restrict__ w,
                 const float* __restrict__ ar, const float* __restrict__ br,
                 const float* __restrict__ ag, const float* __restrict__ bg,
                 const float* __restrict__ ab, const float* __restrict__ bb)
{
    __shared__ float s[Cc][SH][SW];
    __shared__ float sred[8][6];

    const int b  = blockIdx.z;
    const int h0 = blockIdx.y * TH;
    const int w0 = blockIdx.x * TW;
    const int tid = threadIdx.x;

    const float* in = PRE ? (const float*)g_y1 : xin;
    float* outbuf   = PRE ? g_y2 : g_y1;
    float* part     = PRE ? g_part2 : g_part1;

    // ---- fill shared tile (SAME zero padding); PRE applies BN1+rational to
    // in-bounds pixels only (padding stays exactly 0, matching reference) ----
    #pragma unroll
    for (int c = 0; c < Cc; c++) {
        float A = 0.f, Bv = 0.f;
        float a0=0,a1=0,a2=0,a3=0,a4=0,a5=0,q0=0,q1=0,q2=0,q3=0;
        if (PRE) {
            A  = g_bn1[c];
            Bv = g_bn1[3 + c];
            const float* A6 = (c == 0) ? ar : ((c == 1) ? ag : ab);
            const float* B4 = (c == 0) ? br : ((c == 1) ? bg : bb);
            a0 = __ldg(&A6[0]); a1 = __ldg(&A6[1]); a2 = __ldg(&A6[2]);
            a3 = __ldg(&A6[3]); a4 = __ldg(&A6[4]); a5 = __ldg(&A6[5]);
            q0 = __ldg(&B4[0]); q1 = __ldg(&B4[1]); q2 = __ldg(&B4[2]); q3 = __ldg(&B4[3]);
        }
        const float* base = in + ((size_t)b * Cc + c) * NPIX;
        for (int i = tid; i < SH * SW; i += 256) {
            int r   = i / SW;
            int col = i - r * SW;
            int gh = h0 - 1 + r;
            int gw = w0 - 1 + col;
            float v = 0.0f;
            if (gh >= 0 && gh < Hh && gw >= 0 && gw < Ww) {
                v = base[gh * Ww + gw];
                if (PRE) {
                    float t = fmaf(v, A, Bv);
                    v = ratf(t, a0, a1, a2, a3, a4, a5, q0, q1, q2, q3);
                }
            }
            s[c][r][col] = v;
        }
    }
    __syncthreads();

    // ---- weights (OIHW) ----
    float wl[3][3][3][3];
    #pragma unroll
    for (int co = 0; co < 3; co++)
        #pragma unroll
        for (int ci = 0; ci < 3; ci++)
            #pragma unroll
            for (int ky = 0; ky < 3; ky++)
                #pragma unroll
                for (int kx = 0; kx < 3; kx++)
                    wl[co][ci][ky][kx] = __ldg(&w[((co * 3 + ci) * 3 + ky) * 3 + kx]);

    // ---- compute: 4 wide x 2 tall x 3 out-channels per thread, packed f32x2 ----
    const int tx = tid & 15;          // 16 col groups of 4
    const int ty = tid >> 4;          // 16 row groups of 2
    const int col0 = tx * 4;
    const int row0 = ty * 2;

    u64t acc[3][2][2];
    #pragma unroll
    for (int co = 0; co < 3; co++)
        #pragma unroll
        for (int orow = 0; orow < 2; orow++) {
            acc[co][orow][0] = 0ULL;
            acc[co][orow][1] = 0ULL;
        }

    #pragma unroll
    for (int ci = 0; ci < 3; ci++) {
        // 4 input rows x 6 cols as aligned float2 pairs
        float2 q[4][3];
        #pragma unroll
        for (int r = 0; r < 4; r++)
            #pragma unroll
            for (int j = 0; j < 3; j++)
                q[r][j] = *reinterpret_cast<const float2*>(&s[ci][row0 + r][col0 + 2 * j]);

        u64t P[4][3], U1[4], U2[4];
        #pragma unroll
        for (int r = 0; r < 4; r++) {
            #pragma unroll
            for (int j = 0; j < 3; j++)
                P[r][j] = pk2(q[r][j].x, q[r][j].y);
            U1[r] = pk2(q[r][0].y, q[r][1].x);    // cols (1,2)
            U2[r] = pk2(q[r][1].y, q[r][2].x);    // cols (3,4)
        }

        #pragma unroll
        for (int ky = 0; ky < 3; ky++)
            #pragma unroll
            for (int kx = 0; kx < 3; kx++)
                #pragma unroll
                for (int co = 0; co < 3; co++) {
                    float wv = wl[co][ci][ky][kx];
                    u64t wp = pk2(wv, wv);
                    #pragma unroll
                    for (int orow = 0; orow < 2; orow++) {
                        int r = orow + ky;
                        u64t Ap = (kx == 0) ? P[r][0] : ((kx == 1) ? U1[r] : P[r][1]);
                        u64t Bp = (kx == 0) ? P[r][1] : ((kx == 1) ? U2[r] : P[r][2]);
                        acc[co][orow][0] = fma2(wp, Ap, acc[co][orow][0]);
                        acc[co][orow][1] = fma2(wp, Bp, acc[co][orow][1]);
                    }
                }
    }

    // ---- stores + packed stats ----
    float st[6];
    #pragma unroll
    for (int k = 0; k < 6; k++) st[k] = 0.0f;

    #pragma unroll
    for (int co = 0; co < 3; co++) {
        u64t sm = 0ULL, sq = 0ULL;
        #pragma unroll
        for (int orow = 0; orow < 2; orow++) {
            #pragma unroll
            for (int p = 0; p < 2; p++) {
                u64t a = acc[co][orow][p];
                sm = add2(sm, a);
                sq = fma2(a, a, sq);
            }
            float4 o;
            upk2(acc[co][orow][0], o.x, o.y);
            upk2(acc[co][orow][1], o.z, o.w);
            size_t off = ((size_t)b * Cc + co) * NPIX
                       + (size_t)(h0 + row0 + orow) * Ww + (w0 + col0);
            *reinterpret_cast<float4*>(outbuf + off) = o;
        }
        float lo, hi;
        upk2(sm, lo, hi); st[co]     = lo + hi;
        upk2(sq, lo, hi); st[co + 3] = lo + hi;
    }

    // ---- deterministic block reduction ----
    #pragma unroll
    for (int off = 16; off > 0; off >>= 1)
        #pragma unroll
        for (int k = 0; k < 6; k++)
            st[k] += __shfl_down_sync(0xffffffffu, st[k], off);

    const int warp = tid >> 5, lane = tid & 31;
    if (lane == 0)
        #pragma unroll
        for (int k = 0; k < 6; k++) sred[warp][k] = st[k];
    __syncthreads();

    if (tid < 6) {
        float t = 0.0f;
        #pragma unroll
        for (int wp = 0; wp < 8; wp++) t += sred[wp][tid];
        int bid = (blockIdx.z * NB_Y + blockIdx.y) * NB_X + blockIdx.x;
        part[bid * 6 + tid] = t;
    }
}

// Stage A: NPB(=128) partials per image -> 1 double partial per image.
__global__ __launch_bounds__(128)
void reduceA_kernel(int which)
{
    __shared__ double sd[128][6];
    const float* part = which ? g_part2 : g_part1;
    const int tid = threadIdx.x;
    const int base = (blockIdx.x * NPB + tid) * 6;

    #pragma unroll
    for (int k = 0; k < 6; k++) sd[tid][k] = (double)part[base + k];
    __syncthreads();

    #pragma unroll
    for (int off = 64; off > 0; off >>= 1) {
        if (tid < off)
            #pragma unroll
            for (int k = 0; k < 6; k++)
                sd[tid][k] += sd[tid + off][k];
        __syncthreads();
    }

    if (tid < 6) g_mid[blockIdx.x * 6 + tid] = sd[0][tid];
}

// Stage B: reduce B mid-partials, fold BN into per-channel (A, B).
__global__ __launch_bounds__(256)
void reduceB_kernel(const float* __restrict__ gamma, const float* __restrict__ beta,
                    int nmid, double invN, int which)
{
    __shared__ double sd[256][6];
    float* bn = which ? g_bn2 : g_bn1;
    const int tid = threadIdx.x;

    double acc[6] = {0, 0, 0, 0, 0, 0};
    for (int i = tid; i < nmid; i += 256)
        #pragma unroll
        for (int k = 0; k < 6; k++)
            acc[k] += g_mid[i * 6 + k];
    #pragma unroll
    for (int k = 0; k < 6; k++) sd[tid][k] = acc[k];
    __syncthreads();

    #pragma unroll
    for (int off = 128; off > 0; off >>= 1) {
        if (tid < off)
            #pragma unroll
            for (int k = 0; k < 6; k++)
                sd[tid][k] += sd[tid + off][k];
        __syncthreads();
    }

    if (tid < 3) {
        int c = tid;
        double mean = sd[0][c] * invN;
        double var  = sd[0][c + 3] * invN - mean * mean;
        float A = gamma[c] / sqrtf((float)var + 1e-5f);
        bn[c]     = A;
        bn[3 + c] = beta[c] - (float)mean * A;
    }
}

// Epilogue: out = rational_c(A2*y2 + B2 + x), float4 stream.
__global__ __launch_bounds__(256)
void epilogue_kernel(const float* __restrict__ x, float* __restrict__ out,
                     const float* __restrict__ ar, const float* __restrict__ br,
                     const float* __restrict__ ag, const float* __restrict__ bg,
                     const float* __restrict__ ab, const float* __restrict__ bb,
                     int total4)
{
    int i = blockIdx.x * blockDim.x + threadIdx.x;
    if (i >= total4) return;

    int c = (i >> 16) % 3;    // NPIX/4 = 65536 float4 per channel
    float A  = g_bn2[c];
    float Bv = g_bn2[3 + c];
    const float* A6 = (c == 0) ? ar : ((c == 1) ? ag : ab);
    const float* B4 = (c == 0) ? br : ((c == 1) ? bg : bb);
    float a0 = __ldg(&A6[0]), a1 = __ldg(&A6[1]), a2 = __ldg(&A6[2]);
    float a3 = __ldg(&A6[3]), a4 = __ldg(&A6[4]), a5 = __ldg(&A6[5]);
    float q0 = __ldg(&B4[0]), q1 = __ldg(&B4[1]), q2 = __ldg(&B4[2]), q3 = __ldg(&B4[3]);

    float4 y  = reinterpret_cast<const float4*>(g_y2)[i];
    float4 xv = reinterpret_cast<const float4*>(x)[i];

    float4 o;
    o.x = ratf(fmaf(y.x, A, Bv) + xv.x, a0, a1, a2, a3, a4, a5, q0, q1, q2, q3);
    o.y = ratf(fmaf(y.y, A, Bv) + xv.y, a0, a1, a2, a3, a4, a5, q0, q1, q2, q3);
    o.z = ratf(fmaf(y.z, A, Bv) + xv.z, a0, a1, a2, a3, a4, a5, q0, q1, q2, q3);
    o.w = ratf(fmaf(y.w, A, Bv) + xv.w, a0, a1, a2, a3, a4, a5, q0, q1, q2, q3);
    reinterpret_cast<float4*>(out)[i] = o;
}

extern "C" void kernel_launch(void* const* d_in, const int* in_sizes, int n_in,
                              void* d_out, int out_size)
{
    const float* x  = (const float*)d_in[0];
    const float* w1 = (const float*)d_in[1];
    const float* g1 = (const float*)d_in[2];
    const float* b1 = (const float*)d_in[3];
    const float* ar = (const float*)d_in[4];
    const float* br = (const float*)d_in[5];
    const float* ag = (const float*)d_in[6];
    const float* bg = (const float*)d_in[7];
    const float* ab = (const float*)d_in[8];
    const float* bb = (const float*)d_in[9];
    const float* w2 = (const float*)d_in[10];
    const float* g2 = (const float*)d_in[11];
    const float* b2 = (const float*)d_in[12];
    float* out = (float*)d_out;

    const int B = in_sizes[0] / (Cc * NPIX);   // 64
    const double invN = 1.0 / ((double)B * (double)NPIX);

    dim3 grid(NB_X, NB_Y, B), block(256);

    conv_kernel<false><<<grid, block>>>(x, w1, ar, br, ag, bg, ab, bb);
    reduceA_kernel<<<B, 128>>>(0);
    reduceB_kernel<<<1, 256>>>(g1, b1, B, invN, 0);
    conv_kernel<true><<<grid, block>>>(x, w2, ar, br, ag, bg, ab, bb);
    reduceA_kernel<<<B, 128>>>(1);
    reduceB_kernel<<<1, 256>>>(g2, b2, B, invN, 1);

    int total4 = (B * Cc * NPIX) / 4;
    int nb3 = (total4 + 255) / 256;
    epilogue_kernel<<<nb3, 256>>>(x, out, ar, br, ag, bg, ab, bb, total4);
}